// round 15
// baseline (speedup 1.0000x reference)
#include <cuda_runtime.h>
#include <cuda_bf16.h>
#include <cuda_fp16.h>
#include <mma.h>
#include <cstdint>

using namespace nvcuda;

#define D_DIM 512
#define F_DIM 256
#define N_MAX 50000
#define E_MAX 800000
// rows padded to a multiple of 128 so the last GEMM tile can store unguarded
#define PAD_ROWS 100096

// Scratch (static device globals — no allocation allowed)
__device__ float g_support[(size_t)PAD_ROWS * F_DIM];   // [>=2N, F] branch-major
__device__ int   g_rowptr[N_MAX + 1];
__device__ int   g_deg[N_MAX];        // zero-initialized at load; re-zeroed by aggregate
__device__ int   g_cursor[N_MAX];
__device__ int   g_col_sorted[E_MAX];
__device__ float g_val_sorted[E_MAX];

// ===========================================================================
// fp16x3 HMMA GEMM: g_support[r][f] = sum_d feat[r][d] * W[d][f]
// r in [0, 2N): r < N -> feature_ori[r], else feature_aug[r-N]
// CTA tile M=128, N=128 (grid.y selects F half), K chunks of 32.
// x = hi + lo (fp16); accumulate hi*hi + hi*lo + lo*hi in fp32 (wmma).
// __launch_bounds__(256,2): 2 CTAs/SM hide staging & conversion latency.
// ===========================================================================
#define GBM 128
#define GBN 128
#define GBK 32
#define A_LD (GBK + 8)     // halves: 40
#define B_LD (GBN + 8)     // halves: 136

__global__ __launch_bounds__(256, 2)
void gemm_hmma_kernel(const float* __restrict__ ori, const float* __restrict__ aug,
                      const float* __restrict__ W, int N) {
    // [split][...] : split 0 = hi, 1 = lo
    __shared__ __align__(16) __half As[2][GBM * A_LD];
    __shared__ __align__(16) __half Bs[2][GBK * B_LD];

    const int tid = threadIdx.x;
    const int wid = tid >> 5;
    const int block_row = blockIdx.x * GBM;
    const int n0 = blockIdx.y * GBN;

    const int warp_m = wid >> 1;   // 0..3 -> 32-row slice
    const int warp_n = wid & 1;    // 0..1 -> 64-col slice

    wmma::fragment<wmma::accumulator, 16, 16, 16, float> acc[2][4];
    #pragma unroll
    for (int i = 0; i < 2; i++)
        #pragma unroll
        for (int j = 0; j < 4; j++) wmma::fill_fragment(acc[i][j], 0.0f);

    for (int k0 = 0; k0 < D_DIM; k0 += GBK) {
        // ---- stage A tile: 128 rows x 32 k (fp32 -> hi/lo fp16) ----
        #pragma unroll
        for (int q = 0; q < 4; q++) {
            const int idx = tid + q * 256;       // 0..1023 float4 slots
            const int r   = idx >> 3;            // 0..127
            const int c4  = (idx & 7) * 4;       // k offset 0..28
            const int grow = block_row + r;
            float4 v = make_float4(0.f, 0.f, 0.f, 0.f);
            if (grow < N)          v = *(const float4*)(ori + (size_t)grow * D_DIM + k0 + c4);
            else if (grow < 2 * N) v = *(const float4*)(aug + (size_t)(grow - N) * D_DIM + k0 + c4);

            __half hx = __float2half_rn(v.x), hy = __float2half_rn(v.y);
            __half hz = __float2half_rn(v.z), hw = __float2half_rn(v.w);
            __half lx = __float2half_rn(v.x - __half2float(hx));
            __half ly = __float2half_rn(v.y - __half2float(hy));
            __half lz = __float2half_rn(v.z - __half2float(hz));
            __half lw = __float2half_rn(v.w - __half2float(hw));

            const int base = r * A_LD + c4;
            *(__half2*)&As[0][base]     = __halves2half2(hx, hy);
            *(__half2*)&As[0][base + 2] = __halves2half2(hz, hw);
            *(__half2*)&As[1][base]     = __halves2half2(lx, ly);
            *(__half2*)&As[1][base + 2] = __halves2half2(lz, lw);
        }
        // ---- stage B tile: 32 k-rows x 128 n (fp32 -> hi/lo fp16) ----
        #pragma unroll
        for (int q = 0; q < 4; q++) {
            const int idx = tid + q * 256;       // 0..1023
            const int kr  = idx >> 5;            // 0..31
            const int c4  = (idx & 31) * 4;      // 0..124
            float4 v = *(const float4*)(W + (size_t)(k0 + kr) * F_DIM + n0 + c4);

            __half hx = __float2half_rn(v.x), hy = __float2half_rn(v.y);
            __half hz = __float2half_rn(v.z), hw = __float2half_rn(v.w);
            __half lx = __float2half_rn(v.x - __half2float(hx));
            __half ly = __float2half_rn(v.y - __half2float(hy));
            __half lz = __float2half_rn(v.z - __half2float(hz));
            __half lw = __float2half_rn(v.w - __half2float(hw));

            const int base = kr * B_LD + c4;
            *(__half2*)&Bs[0][base]     = __halves2half2(hx, hy);
            *(__half2*)&Bs[0][base + 2] = __halves2half2(hz, hw);
            *(__half2*)&Bs[1][base]     = __halves2half2(lx, ly);
            *(__half2*)&Bs[1][base + 2] = __halves2half2(lz, lw);
        }
        __syncthreads();

        // ---- compute: 3 split combos x 2 k-steps x (2m x 4n) wmma ----
        #pragma unroll
        for (int s = 0; s < 3; s++) {
            const int sa = (s == 2) ? 1 : 0;   // (hi,hi), (hi,lo), (lo,hi)
            const int sb = (s == 1) ? 1 : 0;
            #pragma unroll
            for (int kk = 0; kk < GBK; kk += 16) {
                wmma::fragment<wmma::matrix_a, 16, 16, 16, __half, wmma::row_major> a[2];
                #pragma unroll
                for (int i = 0; i < 2; i++)
                    wmma::load_matrix_sync(a[i],
                        &As[sa][(warp_m * 32 + i * 16) * A_LD + kk], A_LD);
                #pragma unroll
                for (int j = 0; j < 4; j++) {
                    wmma::fragment<wmma::matrix_b, 16, 16, 16, __half, wmma::row_major> b;
                    wmma::load_matrix_sync(b,
                        &Bs[sb][kk * B_LD + warp_n * 64 + j * 16], B_LD);
                    #pragma unroll
                    for (int i = 0; i < 2; i++)
                        wmma::mma_sync(acc[i][j], a[i], b, acc[i][j]);
                }
            }
        }
        __syncthreads();
    }

    // ---- store accumulators (rows padded; no bounds check needed) ----
    #pragma unroll
    for (int i = 0; i < 2; i++) {
        const int r = block_row + warp_m * 32 + i * 16;
        #pragma unroll
        for (int j = 0; j < 4; j++) {
            const int c = n0 + warp_n * 64 + j * 16;
            wmma::store_matrix_sync(g_support + (size_t)r * F_DIM + c,
                                    acc[i][j], F_DIM, wmma::mem_row_major);
        }
    }
}

// ---------------------------------------------------------------------------
// CSR build (g_deg is zeroed by the previous call's aggregate_kernel,
// and statically zero on the very first call)
// ---------------------------------------------------------------------------
__global__ void hist_kernel(const int* __restrict__ erow, int E) {
    int e = blockIdx.x * blockDim.x + threadIdx.x;
    if (e < E) atomicAdd(&g_deg[erow[e]], 1);
}

__global__ void scan_kernel(int N) {
    __shared__ int sdata[1024];
    __shared__ int carry;
    const int tid = threadIdx.x;
    if (tid == 0) carry = 0;
    __syncthreads();

    for (int base = 0; base < N; base += 1024) {
        int v = (base + tid < N) ? g_deg[base + tid] : 0;
        sdata[tid] = v;
        __syncthreads();
        #pragma unroll
        for (int off = 1; off < 1024; off <<= 1) {
            int t = (tid >= off) ? sdata[tid - off] : 0;
            __syncthreads();
            sdata[tid] += t;
            __syncthreads();
        }
        int excl = sdata[tid] - v + carry;
        if (base + tid < N) {
            g_rowptr[base + tid] = excl;
            g_cursor[base + tid] = excl;
        }
        __syncthreads();
        if (tid == 1023) carry += sdata[1023];
        __syncthreads();
    }
    if (tid == 0) g_rowptr[N] = carry;
}

__global__ void scatter_sort_kernel(const int* __restrict__ erow,
                                    const int* __restrict__ ecol,
                                    const float* __restrict__ eval_, int E) {
    int e = blockIdx.x * blockDim.x + threadIdx.x;
    if (e >= E) return;
    int r = erow[e];
    int pos = atomicAdd(&g_cursor[r], 1);
    g_col_sorted[pos] = ecol[e];
    g_val_sorted[pos] = eval_[e];
}

// ---------------------------------------------------------------------------
// Aggregate, both branches fused: one block (128 thr) per row.
// threads 0..63  -> branch 0, float4 feature slot (tid&63)
// threads 64..127-> branch 1, same slots
// out[b][row][f] = relu(bias[f] + sum_e val[e] * support[b][col[e]][f])
// Also re-zeros g_deg[row] for the next call.
// ---------------------------------------------------------------------------
__global__ __launch_bounds__(128)
void aggregate_kernel(const float* __restrict__ bias, float* __restrict__ out, int N) {
    const int row = blockIdx.x;
    const int tid = threadIdx.x;
    if (tid == 0) g_deg[row] = 0;     // reset for next kernel_launch call

    const int start = g_rowptr[row];
    const int end   = g_rowptr[row + 1];

    const int grp = tid >> 6;         // branch 0 or 1
    const int f4  = tid & 63;         // float4 slot (feature = f4*4)

    // base pointer: support rows of this branch, offset to this thread's float4
    const float4* sup = (const float4*)(g_support + (size_t)grp * N * F_DIM) + f4;

    __shared__ int   s_col[128];
    __shared__ float s_val[128];

    float4 acc = make_float4(0.f, 0.f, 0.f, 0.f);

    for (int base = start; base < end; base += 128) {
        const int n = min(128, end - base);
        if (tid < n) {
            s_col[tid] = g_col_sorted[base + tid];
            s_val[tid] = g_val_sorted[base + tid];
        }
        __syncthreads();

        int e = 0;
        for (; e + 4 <= n; e += 4) {
            const int   c0 = s_col[e],     c1 = s_col[e + 1];
            const int   c2 = s_col[e + 2], c3 = s_col[e + 3];
            const float v0 = s_val[e],     v1 = s_val[e + 1];
            const float v2 = s_val[e + 2], v3 = s_val[e + 3];
            float4 s0 = __ldg(sup + (size_t)c0 * 64);
            float4 s1 = __ldg(sup + (size_t)c1 * 64);
            float4 s2 = __ldg(sup + (size_t)c2 * 64);
            float4 s3 = __ldg(sup + (size_t)c3 * 64);
            acc.x = fmaf(v0, s0.x, acc.x); acc.y = fmaf(v0, s0.y, acc.y);
            acc.z = fmaf(v0, s0.z, acc.z); acc.w = fmaf(v0, s0.w, acc.w);
            acc.x = fmaf(v1, s1.x, acc.x); acc.y = fmaf(v1, s1.y, acc.y);
            acc.z = fmaf(v1, s1.z, acc.z); acc.w = fmaf(v1, s1.w, acc.w);
            acc.x = fmaf(v2, s2.x, acc.x); acc.y = fmaf(v2, s2.y, acc.y);
            acc.z = fmaf(v2, s2.z, acc.z); acc.w = fmaf(v2, s2.w, acc.w);
            acc.x = fmaf(v3, s3.x, acc.x); acc.y = fmaf(v3, s3.y, acc.y);
            acc.z = fmaf(v3, s3.z, acc.z); acc.w = fmaf(v3, s3.w, acc.w);
        }
        for (; e < n; e++) {
            const int   c = s_col[e];
            const float v = s_val[e];
            float4 s = __ldg(sup + (size_t)c * 64);
            acc.x = fmaf(v, s.x, acc.x); acc.y = fmaf(v, s.y, acc.y);
            acc.z = fmaf(v, s.z, acc.z); acc.w = fmaf(v, s.w, acc.w);
        }
        __syncthreads();
    }

    const float4 bv = *(const float4*)(bias + f4 * 4);
    acc.x = fmaxf(acc.x + bv.x, 0.f);
    acc.y = fmaxf(acc.y + bv.y, 0.f);
    acc.z = fmaxf(acc.z + bv.z, 0.f);
    acc.w = fmaxf(acc.w + bv.w, 0.f);
    *(float4*)(out + ((size_t)grp * N + row) * F_DIM + f4 * 4) = acc;
}

extern "C" void kernel_launch(void* const* d_in, const int* in_sizes, int n_in,
                              void* d_out, int out_size) {
    const float* feature_ori = (const float*)d_in[0];
    const float* feature_aug = (const float*)d_in[1];
    const int*   edge_row    = (const int*)d_in[2];
    const int*   edge_col    = (const int*)d_in[3];
    const float* edge_val    = (const float*)d_in[4];
    const float* weight      = (const float*)d_in[5];
    const float* bias        = (const float*)d_in[6];
    float* out = (float*)d_out;

    const int N = in_sizes[0] / D_DIM;   // 50000
    const int E = in_sizes[2];           // 800000

    // 1) histogram (g_deg zeroed by previous call's aggregate / static init)
    hist_kernel<<<(E + 255) / 256, 256>>>(edge_row, E);
    // 2) exclusive scan -> rowptr, cursor
    scan_kernel<<<1, 1024>>>(N);
    // 3) bucket-sort edges by row
    scatter_sort_kernel<<<(E + 255) / 256, 256>>>(edge_row, edge_col, edge_val, E);
    // 4) GEMM -> g_support [2N, F]   (slot 4: captured by ncu)
    {
        dim3 grid((2 * N + GBM - 1) / GBM, F_DIM / GBN);
        gemm_hmma_kernel<<<grid, 256>>>(feature_ori, feature_aug, weight, N);
    }
    // 5) fused aggregate + bias + relu (also re-zeros g_deg)
    {
        aggregate_kernel<<<N, 128>>>(bias, out, N);
    }
}

// round 17
// speedup vs baseline: 1.0000x; 1.0000x over previous
#include <cuda_runtime.h>
#include <cuda_bf16.h>
#include <cuda_fp16.h>
#include <mma.h>
#include <cstdint>

using namespace nvcuda;

#define D_DIM 512
#define F_DIM 256
#define N_MAX 50000
#define E_MAX 800000
// rows padded to a multiple of 128 so the last GEMM tile can store unguarded
#define PAD_ROWS 100096

// Scratch (static device globals — no allocation allowed)
__device__ float g_support[(size_t)PAD_ROWS * F_DIM];   // [>=2N, F] branch-major
__device__ int   g_rowptr[N_MAX + 1];
__device__ int   g_deg[N_MAX];        // zero-initialized at load; re-zeroed by aggregate
__device__ int   g_cursor[N_MAX];
__device__ int   g_col_sorted[E_MAX];
__device__ float g_val_sorted[E_MAX];

// ===========================================================================
// fp16x3 HMMA GEMM: g_support[r][f] = sum_d feat[r][d] * W[d][f]
// r in [0, 2N): r < N -> feature_ori[r], else feature_aug[r-N]
// CTA tile M=128, N=128 (grid.y selects F half), K chunks of 32.
// x = hi + lo (fp16); accumulate hi*hi + hi*lo + lo*hi in fp32 (wmma).
// __launch_bounds__(256,2): 2 CTAs/SM hide staging & conversion latency.
// ===========================================================================
#define GBM 128
#define GBN 128
#define GBK 32
#define A_LD (GBK + 8)     // halves: 40
#define B_LD (GBN + 8)     // halves: 136

__global__ __launch_bounds__(256, 2)
void gemm_hmma_kernel(const float* __restrict__ ori, const float* __restrict__ aug,
                      const float* __restrict__ W, int N) {
    // [split][...] : split 0 = hi, 1 = lo
    __shared__ __align__(16) __half As[2][GBM * A_LD];
    __shared__ __align__(16) __half Bs[2][GBK * B_LD];

    const int tid = threadIdx.x;
    const int wid = tid >> 5;
    const int block_row = blockIdx.x * GBM;
    const int n0 = blockIdx.y * GBN;

    const int warp_m = wid >> 1;   // 0..3 -> 32-row slice
    const int warp_n = wid & 1;    // 0..1 -> 64-col slice

    wmma::fragment<wmma::accumulator, 16, 16, 16, float> acc[2][4];
    #pragma unroll
    for (int i = 0; i < 2; i++)
        #pragma unroll
        for (int j = 0; j < 4; j++) wmma::fill_fragment(acc[i][j], 0.0f);

    for (int k0 = 0; k0 < D_DIM; k0 += GBK) {
        // ---- stage A tile: 128 rows x 32 k (fp32 -> hi/lo fp16) ----
        #pragma unroll
        for (int q = 0; q < 4; q++) {
            const int idx = tid + q * 256;       // 0..1023 float4 slots
            const int r   = idx >> 3;            // 0..127
            const int c4  = (idx & 7) * 4;       // k offset 0..28
            const int grow = block_row + r;
            float4 v = make_float4(0.f, 0.f, 0.f, 0.f);
            if (grow < N)          v = *(const float4*)(ori + (size_t)grow * D_DIM + k0 + c4);
            else if (grow < 2 * N) v = *(const float4*)(aug + (size_t)(grow - N) * D_DIM + k0 + c4);

            __half hx = __float2half_rn(v.x), hy = __float2half_rn(v.y);
            __half hz = __float2half_rn(v.z), hw = __float2half_rn(v.w);
            __half lx = __float2half_rn(v.x - __half2float(hx));
            __half ly = __float2half_rn(v.y - __half2float(hy));
            __half lz = __float2half_rn(v.z - __half2float(hz));
            __half lw = __float2half_rn(v.w - __half2float(hw));

            const int base = r * A_LD + c4;
            *(__half2*)&As[0][base]     = __halves2half2(hx, hy);
            *(__half2*)&As[0][base + 2] = __halves2half2(hz, hw);
            *(__half2*)&As[1][base]     = __halves2half2(lx, ly);
            *(__half2*)&As[1][base + 2] = __halves2half2(lz, lw);
        }
        // ---- stage B tile: 32 k-rows x 128 n (fp32 -> hi/lo fp16) ----
        #pragma unroll
        for (int q = 0; q < 4; q++) {
            const int idx = tid + q * 256;       // 0..1023
            const int kr  = idx >> 5;            // 0..31
            const int c4  = (idx & 31) * 4;      // 0..124
            float4 v = *(const float4*)(W + (size_t)(k0 + kr) * F_DIM + n0 + c4);

            __half hx = __float2half_rn(v.x), hy = __float2half_rn(v.y);
            __half hz = __float2half_rn(v.z), hw = __float2half_rn(v.w);
            __half lx = __float2half_rn(v.x - __half2float(hx));
            __half ly = __float2half_rn(v.y - __half2float(hy));
            __half lz = __float2half_rn(v.z - __half2float(hz));
            __half lw = __float2half_rn(v.w - __half2float(hw));

            const int base = kr * B_LD + c4;
            *(__half2*)&Bs[0][base]     = __halves2half2(hx, hy);
            *(__half2*)&Bs[0][base + 2] = __halves2half2(hz, hw);
            *(__half2*)&Bs[1][base]     = __halves2half2(lx, ly);
            *(__half2*)&Bs[1][base + 2] = __halves2half2(lz, lw);
        }
        __syncthreads();

        // ---- compute: 3 split combos x 2 k-steps x (2m x 4n) wmma ----
        #pragma unroll
        for (int s = 0; s < 3; s++) {
            const int sa = (s == 2) ? 1 : 0;   // (hi,hi), (hi,lo), (lo,hi)
            const int sb = (s == 1) ? 1 : 0;
            #pragma unroll
            for (int kk = 0; kk < GBK; kk += 16) {
                wmma::fragment<wmma::matrix_a, 16, 16, 16, __half, wmma::row_major> a[2];
                #pragma unroll
                for (int i = 0; i < 2; i++)
                    wmma::load_matrix_sync(a[i],
                        &As[sa][(warp_m * 32 + i * 16) * A_LD + kk], A_LD);
                #pragma unroll
                for (int j = 0; j < 4; j++) {
                    wmma::fragment<wmma::matrix_b, 16, 16, 16, __half, wmma::row_major> b;
                    wmma::load_matrix_sync(b,
                        &Bs[sb][kk * B_LD + warp_n * 64 + j * 16], B_LD);
                    #pragma unroll
                    for (int i = 0; i < 2; i++)
                        wmma::mma_sync(acc[i][j], a[i], b, acc[i][j]);
                }
            }
        }
        __syncthreads();
    }

    // ---- store accumulators (rows padded; no bounds check needed) ----
    #pragma unroll
    for (int i = 0; i < 2; i++) {
        const int r = block_row + warp_m * 32 + i * 16;
        #pragma unroll
        for (int j = 0; j < 4; j++) {
            const int c = n0 + warp_n * 64 + j * 16;
            wmma::store_matrix_sync(g_support + (size_t)r * F_DIM + c,
                                    acc[i][j], F_DIM, wmma::mem_row_major);
        }
    }
}

// ---------------------------------------------------------------------------
// CSR build (g_deg is zeroed by the previous call's aggregate_kernel,
// and statically zero on the very first call)
// ---------------------------------------------------------------------------
__global__ void hist_kernel(const int* __restrict__ erow, int E) {
    int e = blockIdx.x * blockDim.x + threadIdx.x;
    if (e < E) atomicAdd(&g_deg[erow[e]], 1);
}

__global__ void scan_kernel(int N) {
    __shared__ int sdata[1024];
    __shared__ int carry;
    const int tid = threadIdx.x;
    if (tid == 0) carry = 0;
    __syncthreads();

    for (int base = 0; base < N; base += 1024) {
        int v = (base + tid < N) ? g_deg[base + tid] : 0;
        sdata[tid] = v;
        __syncthreads();
        #pragma unroll
        for (int off = 1; off < 1024; off <<= 1) {
            int t = (tid >= off) ? sdata[tid - off] : 0;
            __syncthreads();
            sdata[tid] += t;
            __syncthreads();
        }
        int excl = sdata[tid] - v + carry;
        if (base + tid < N) {
            g_rowptr[base + tid] = excl;
            g_cursor[base + tid] = excl;
        }
        __syncthreads();
        if (tid == 1023) carry += sdata[1023];
        __syncthreads();
    }
    if (tid == 0) g_rowptr[N] = carry;
}

__global__ void scatter_sort_kernel(const int* __restrict__ erow,
                                    const int* __restrict__ ecol,
                                    const float* __restrict__ eval_, int E) {
    int e = blockIdx.x * blockDim.x + threadIdx.x;
    if (e >= E) return;
    int r = erow[e];
    int pos = atomicAdd(&g_cursor[r], 1);
    g_col_sorted[pos] = ecol[e];
    g_val_sorted[pos] = eval_[e];
}

// ---------------------------------------------------------------------------
// Aggregate, both branches fused: one block (128 thr) per row.
// threads 0..63  -> branch 0, float4 feature slot (tid&63)
// threads 64..127-> branch 1, same slots
// out[b][row][f] = relu(bias[f] + sum_e val[e] * support[b][col[e]][f])
// Also re-zeros g_deg[row] for the next call.
// ---------------------------------------------------------------------------
__global__ __launch_bounds__(128)
void aggregate_kernel(const float* __restrict__ bias, float* __restrict__ out, int N) {
    const int row = blockIdx.x;
    const int tid = threadIdx.x;
    if (tid == 0) g_deg[row] = 0;     // reset for next kernel_launch call

    const int start = g_rowptr[row];
    const int end   = g_rowptr[row + 1];

    const int grp = tid >> 6;         // branch 0 or 1
    const int f4  = tid & 63;         // float4 slot (feature = f4*4)

    // base pointer: support rows of this branch, offset to this thread's float4
    const float4* sup = (const float4*)(g_support + (size_t)grp * N * F_DIM) + f4;

    __shared__ int   s_col[128];
    __shared__ float s_val[128];

    float4 acc = make_float4(0.f, 0.f, 0.f, 0.f);

    for (int base = start; base < end; base += 128) {
        const int n = min(128, end - base);
        if (tid < n) {
            s_col[tid] = g_col_sorted[base + tid];
            s_val[tid] = g_val_sorted[base + tid];
        }
        __syncthreads();

        int e = 0;
        for (; e + 4 <= n; e += 4) {
            const int   c0 = s_col[e],     c1 = s_col[e + 1];
            const int   c2 = s_col[e + 2], c3 = s_col[e + 3];
            const float v0 = s_val[e],     v1 = s_val[e + 1];
            const float v2 = s_val[e + 2], v3 = s_val[e + 3];
            float4 s0 = __ldg(sup + (size_t)c0 * 64);
            float4 s1 = __ldg(sup + (size_t)c1 * 64);
            float4 s2 = __ldg(sup + (size_t)c2 * 64);
            float4 s3 = __ldg(sup + (size_t)c3 * 64);
            acc.x = fmaf(v0, s0.x, acc.x); acc.y = fmaf(v0, s0.y, acc.y);
            acc.z = fmaf(v0, s0.z, acc.z); acc.w = fmaf(v0, s0.w, acc.w);
            acc.x = fmaf(v1, s1.x, acc.x); acc.y = fmaf(v1, s1.y, acc.y);
            acc.z = fmaf(v1, s1.z, acc.z); acc.w = fmaf(v1, s1.w, acc.w);
            acc.x = fmaf(v2, s2.x, acc.x); acc.y = fmaf(v2, s2.y, acc.y);
            acc.z = fmaf(v2, s2.z, acc.z); acc.w = fmaf(v2, s2.w, acc.w);
            acc.x = fmaf(v3, s3.x, acc.x); acc.y = fmaf(v3, s3.y, acc.y);
            acc.z = fmaf(v3, s3.z, acc.z); acc.w = fmaf(v3, s3.w, acc.w);
        }
        for (; e < n; e++) {
            const int   c = s_col[e];
            const float v = s_val[e];
            float4 s = __ldg(sup + (size_t)c * 64);
            acc.x = fmaf(v, s.x, acc.x); acc.y = fmaf(v, s.y, acc.y);
            acc.z = fmaf(v, s.z, acc.z); acc.w = fmaf(v, s.w, acc.w);
        }
        __syncthreads();
    }

    const float4 bv = *(const float4*)(bias + f4 * 4);
    acc.x = fmaxf(acc.x + bv.x, 0.f);
    acc.y = fmaxf(acc.y + bv.y, 0.f);
    acc.z = fmaxf(acc.z + bv.z, 0.f);
    acc.w = fmaxf(acc.w + bv.w, 0.f);
    *(float4*)(out + ((size_t)grp * N + row) * F_DIM + f4 * 4) = acc;
}

extern "C" void kernel_launch(void* const* d_in, const int* in_sizes, int n_in,
                              void* d_out, int out_size) {
    const float* feature_ori = (const float*)d_in[0];
    const float* feature_aug = (const float*)d_in[1];
    const int*   edge_row    = (const int*)d_in[2];
    const int*   edge_col    = (const int*)d_in[3];
    const float* edge_val    = (const float*)d_in[4];
    const float* weight      = (const float*)d_in[5];
    const float* bias        = (const float*)d_in[6];
    float* out = (float*)d_out;

    const int N = in_sizes[0] / D_DIM;   // 50000
    const int E = in_sizes[2];           // 800000

    // 1) histogram (g_deg zeroed by previous call's aggregate / static init)
    hist_kernel<<<(E + 255) / 256, 256>>>(edge_row, E);
    // 2) exclusive scan -> rowptr, cursor
    scan_kernel<<<1, 1024>>>(N);
    // 3) bucket-sort edges by row
    scatter_sort_kernel<<<(E + 255) / 256, 256>>>(edge_row, edge_col, edge_val, E);
    // 4) GEMM -> g_support [2N, F]   (slot 4: captured by ncu)
    {
        dim3 grid((2 * N + GBM - 1) / GBM, F_DIM / GBN);
        gemm_hmma_kernel<<<grid, 256>>>(feature_ori, feature_aug, weight, N);
    }
    // 5) fused aggregate + bias + relu (also re-zeros g_deg)
    {
        aggregate_kernel<<<N, 128>>>(bias, out, N);
    }
}